// round 15
// baseline (speedup 1.0000x reference)
#include <cuda_runtime.h>
#include <cuda_bf16.h>
#include <cstddef>
#include <climits>

// Problem constants (fixed by the reference setup)
#define BB      16
#define TRED    512
#define CC      512
#define C4      (CC / 4)   // float4 per row = 128
#define TT      128        // t-rows per block
#define NTH     512        // threads per block
#define NWARP   (NTH / 32) // 16
#define RPW     (NTH / C4) // 4 row-groups
#define NJ      (TT / RPW) // 32 consecutive rows per thread

// One fused kernel.
//   head: 512-wide inclusive scan of durations[b] via warp shfl (3 syncs),
//         searchsorted seg for the block's TT rows, mask write.
//   body: each thread walks NJ=32 CONSECUTIVE t-rows of its column slice.
//         Since avg duration ~8.5, seg changes only every ~8 rows: reload the
//         gather row only on seg change (warp-uniform branch), reuse the
//         register value otherwise. Cuts L2 gather-read traffic ~7x; the
//         kernel becomes a nearly pure store stream.
__global__ __launch_bounds__(NTH)
void upsample_fused(const float* __restrict__ px,
                    const int*   __restrict__ dur,
                    const int*   __restrict__ target_T,
                    float*       __restrict__ out,
                    int max_len, int write_mask)
{
    __shared__ int csum[TRED];
    __shared__ int wsum[NWARP];
    __shared__ int seg_s[TT];

    const int b    = blockIdx.y;
    const int tid  = threadIdx.x;
    const int lane = tid & 31;
    const int wid  = tid >> 5;
    const int t0   = blockIdx.x * TT;

    // ---- inclusive scan of durations[b] (warp shfl scan, 3 syncs) ----
    int x = dur[b * TRED + tid];
    #pragma unroll
    for (int off = 1; off < 32; off <<= 1) {
        int y = __shfl_up_sync(0xffffffffu, x, off);
        if (lane >= off) x += y;
    }
    if (lane == 31) wsum[wid] = x;
    __syncthreads();
    if (wid == 0) {
        int w = (lane < NWARP) ? wsum[lane] : 0;
        #pragma unroll
        for (int off = 1; off < NWARP; off <<= 1) {
            int y = __shfl_up_sync(0xffffffffu, w, off);
            if (lane >= off) w += y;
        }
        if (lane < NWARP) wsum[lane] = w;
    }
    __syncthreads();
    csum[tid] = x + ((wid > 0) ? wsum[wid - 1] : 0);
    __syncthreads();

    const int total    = csum[TRED - 1];
    const int curr_len = min(total, target_T[b]);   // == total by construction

    // ---- first TT threads: searchsorted + mask write ----
    if (tid < TT) {
        const int t     = t0 + tid;
        const int valid = (t < max_len) && (t < curr_len);
        int seg = -1;
        if (valid) {
            int lo = 0, hi = TRED;                   // first i with csum[i] > t
            while (lo < hi) {
                int mid = (lo + hi) >> 1;
                if (csum[mid] > t) hi = mid; else lo = mid + 1;
            }
            seg = min(lo, TRED - 1);
        }
        seg_s[tid] = seg;
        if (write_mask && t < max_len) {
            float* mask = out + (size_t)BB * max_len * CC;
            mask[(size_t)b * max_len + t] = valid ? 0.0f : 1.0f;
        }
    }
    __syncthreads();

    // ---- hot loop: thread owns NJ consecutive rows of one column slice ----
    const int grp = tid >> 7;        // 0..3
    const int c4  = tid & (C4 - 1);  // 0..127
    const int r0  = grp * NJ;        // first local row for this thread
    const float4* pxb  = (const float4*)px + (size_t)b * TRED * C4 + c4;
    float4*       outp = (float4*)out + ((size_t)b * max_len + t0 + r0) * C4 + c4;
    const float4  Z    = make_float4(0.0f, 0.0f, 0.0f, 0.0f);

    int    s_prev = INT_MIN;
    float4 v      = Z;

    if (t0 + TT <= max_len) {
        // fast path: full tile, no per-row bounds checks
        #pragma unroll
        for (int j = 0; j < NJ; j++) {
            const int s = seg_s[r0 + j];             // warp-uniform
            if (s != s_prev) {                       // warp-uniform branch
                v = (s >= 0) ? __ldg(&pxb[(size_t)s * C4]) : Z;
                s_prev = s;
            }
            outp[(size_t)j * C4] = v;
        }
    } else {
        // tail block: guarded
        #pragma unroll
        for (int j = 0; j < NJ; j++) {
            const int t = t0 + r0 + j;
            if (t >= max_len) break;                 // rows are consecutive
            const int s = seg_s[r0 + j];
            if (s != s_prev) {
                v = (s >= 0) ? __ldg(&pxb[(size_t)s * C4]) : Z;
                s_prev = s;
            }
            outp[(size_t)j * C4] = v;
        }
    }
}

extern "C" void kernel_launch(void* const* d_in, const int* in_sizes, int n_in,
                              void* d_out, int out_size)
{
    const float* px  = (const float*)d_in[0];   // pooled_x  (B, T_RED, C) f32
    const int*   dur = (const int*)  d_in[1];   // durations (B, T_RED)   i32
    const int*   tgt = (const int*)  d_in[2];   // target_T  (B,)         i32

    // Recover max_len from out_size. Layout: [x (B*max_len*C)] ++ [mask (B*max_len)].
    int max_len, write_mask;
    if (out_size % (BB * (CC + 1)) == 0) {
        max_len    = out_size / (BB * (CC + 1));
        write_mask = 1;
    } else {
        max_len    = out_size / (BB * CC);   // fallback: x-only output
        write_mask = 0;
    }

    dim3 grid((max_len + TT - 1) / TT, BB);
    upsample_fused<<<grid, NTH>>>(px, dur, tgt, (float*)d_out, max_len, write_mask);
}

// round 16
// speedup vs baseline: 1.1271x; 1.1271x over previous
#include <cuda_runtime.h>
#include <cuda_bf16.h>
#include <cstddef>

// Problem constants (fixed by the reference setup)
#define BB      16
#define TRED    512
#define CC      512
#define C4      (CC / 4)   // float4 per row = 128
#define TT      64         // t-rows per block
#define NTH     512        // threads per block
#define NWARP   (NTH / 32) // 16
#define RPW     (NTH / C4) // 4 rows in flight per wave
#define NJ      (TT / RPW) // 16 waves per thread

// Fused kernel with a block-uniform pure-padding fast path.
//   padding blocks (t0 >= target_T[b], implies t >= curr_len for the whole
//   tile since curr_len = min(total, target) <= target): no duration load, no
//   scan, no syncs — just stream zeros + mask=1. ~20-24% of all blocks.
//   real blocks: shfl-scan head (3 syncs) + searchsorted + batched-4
//   LDG.128/STG.128 gather body (MLP=4/thread).
__global__ __launch_bounds__(NTH)
void upsample_fused(const float* __restrict__ px,
                    const int*   __restrict__ dur,
                    const int*   __restrict__ target_T,
                    float*       __restrict__ out,
                    int max_len, int write_mask)
{
    __shared__ int csum[TRED];
    __shared__ int wsum[NWARP];
    __shared__ int seg_s[TT];

    const int b    = blockIdx.y;
    const int tid  = threadIdx.x;
    const int t0   = blockIdx.x * TT;
    const int tgt  = target_T[b];

    const float4 Z = make_float4(0.0f, 0.0f, 0.0f, 0.0f);
    const int row  = tid >> 7;        // 0..3
    const int c4   = tid & (C4 - 1);  // 0..127
    float4* outp = (float4*)out + ((size_t)b * max_len + t0 + row) * C4 + c4;
    float*  mask = out + (size_t)BB * max_len * CC;

    // ---------- pure-padding fast path (block-uniform condition) ----------
    if (t0 >= tgt) {
        if (write_mask && tid < TT && t0 + tid < max_len)
            mask[(size_t)b * max_len + t0 + tid] = 1.0f;
        if (t0 + TT <= max_len) {
            #pragma unroll
            for (int j = 0; j < NJ; j++)
                outp[(size_t)j * RPW * C4] = Z;
        } else {
            #pragma unroll
            for (int j = 0; j < NJ; j++) {
                if (t0 + row + j * RPW < max_len)
                    outp[(size_t)j * RPW * C4] = Z;
            }
        }
        return;
    }

    // ---------- real block: scan + search + gather ----------
    const int lane = tid & 31;
    const int wid  = tid >> 5;

    // inclusive scan of durations[b] (warp shfl scan, 3 syncs)
    int x = dur[b * TRED + tid];
    #pragma unroll
    for (int off = 1; off < 32; off <<= 1) {
        int y = __shfl_up_sync(0xffffffffu, x, off);
        if (lane >= off) x += y;
    }
    if (lane == 31) wsum[wid] = x;
    __syncthreads();
    if (wid == 0) {
        int w = (lane < NWARP) ? wsum[lane] : 0;
        #pragma unroll
        for (int off = 1; off < NWARP; off <<= 1) {
            int y = __shfl_up_sync(0xffffffffu, w, off);
            if (lane >= off) w += y;
        }
        if (lane < NWARP) wsum[lane] = w;
    }
    __syncthreads();
    csum[tid] = x + ((wid > 0) ? wsum[wid - 1] : 0);
    __syncthreads();

    const int total    = csum[TRED - 1];
    const int curr_len = min(total, tgt);

    // first TT threads: searchsorted + mask write
    if (tid < TT) {
        const int t     = t0 + tid;
        const int valid = (t < max_len) && (t < curr_len);
        int seg = -1;
        if (valid) {
            int lo = 0, hi = TRED;                   // first i with csum[i] > t
            while (lo < hi) {
                int mid = (lo + hi) >> 1;
                if (csum[mid] > t) hi = mid; else lo = mid + 1;
            }
            seg = min(lo, TRED - 1);
        }
        seg_s[tid] = seg;
        if (write_mask && t < max_len)
            mask[(size_t)b * max_len + t] = valid ? 0.0f : 1.0f;
    }
    __syncthreads();

    // hot loop: 128 threads per row, RPW=4 rows/wave, batched 4-deep (MLP=4)
    const float4* pxb = (const float4*)px + (size_t)b * TRED * C4 + c4;

    if (t0 + TT <= max_len) {
        #pragma unroll
        for (int j = 0; j < NJ; j += 4) {
            const int s0 = seg_s[row + (j + 0) * RPW];
            const int s1 = seg_s[row + (j + 1) * RPW];
            const int s2 = seg_s[row + (j + 2) * RPW];
            const int s3 = seg_s[row + (j + 3) * RPW];
            float4 v0 = (s0 >= 0) ? pxb[(size_t)s0 * C4] : Z;
            float4 v1 = (s1 >= 0) ? pxb[(size_t)s1 * C4] : Z;
            float4 v2 = (s2 >= 0) ? pxb[(size_t)s2 * C4] : Z;
            float4 v3 = (s3 >= 0) ? pxb[(size_t)s3 * C4] : Z;
            outp[(size_t)(j + 0) * RPW * C4] = v0;
            outp[(size_t)(j + 1) * RPW * C4] = v1;
            outp[(size_t)(j + 2) * RPW * C4] = v2;
            outp[(size_t)(j + 3) * RPW * C4] = v3;
        }
    } else {
        #pragma unroll
        for (int j = 0; j < NJ; j++) {
            const int t = t0 + row + j * RPW;
            if (t >= max_len) continue;
            const int s = seg_s[row + j * RPW];
            float4 v = (s >= 0) ? pxb[(size_t)s * C4] : Z;
            outp[(size_t)j * RPW * C4] = v;
        }
    }
}

extern "C" void kernel_launch(void* const* d_in, const int* in_sizes, int n_in,
                              void* d_out, int out_size)
{
    const float* px  = (const float*)d_in[0];   // pooled_x  (B, T_RED, C) f32
    const int*   dur = (const int*)  d_in[1];   // durations (B, T_RED)   i32
    const int*   tgt = (const int*)  d_in[2];   // target_T  (B,)         i32

    // Recover max_len from out_size. Layout: [x (B*max_len*C)] ++ [mask (B*max_len)].
    int max_len, write_mask;
    if (out_size % (BB * (CC + 1)) == 0) {
        max_len    = out_size / (BB * (CC + 1));
        write_mask = 1;
    } else {
        max_len    = out_size / (BB * CC);   // fallback: x-only output
        write_mask = 0;
    }

    dim3 grid((max_len + TT - 1) / TT, BB);
    upsample_fused<<<grid, NTH>>>(px, dur, tgt, (float*)d_out, max_len, write_mask);
}